// round 12
// baseline (speedup 1.0000x reference)
#include <cuda_runtime.h>
#include <cuda_bf16.h>
#include <math_constants.h>

// Problem constants
#define T_TOKENS 4096
#define HIDDEN   2048
#define N_EXP    8
#define H4       (HIDDEN / 4)          // 512 float4 per hidden row
#define H4_HALF  (H4 / 2)              // 256 float4 per half

// Output layout (floats), outputs concatenated:
//   [0, 32768)                router_scores [E, T]
//   [32768, +67108864)        router_indices [E*T, H] (value = t, as float)
//   [67141632, 67174400)      router_probs [E*T, 1] == scores flattened
#define SCORES_OFF 0
#define IDX_OFF    (N_EXP * T_TOKENS)                       // 32768
#define IDX_ELEMS  ((size_t)N_EXP * T_TOKENS * HIDDEN)      // 67108864
#define PROBS_OFF  (IDX_OFF + IDX_ELEMS)                    // 67141632

// Fused grid, blockDim = 256:
//   ids [0, 512)      logits blocks: 8 warps; warps 0-3 = tokens x half0,
//                     warps 4-7 = same tokens x half1. 8 tokens/block.
//                     Per-warp chain is HALF of R8's -> logits CTA ~2x shorter.
//   ids [512, 16896)  fill blocks: 256 thr x 4 float4 = 1024 f4 = 4 KB/block
//                     (same per-block bytes as R8's known-good fill).
#define LOGITS_BLOCKS 512
#define TPW 2
#define FILL_F4_PER_THREAD 4
#define FILL_F4_PER_BLOCK (256 * FILL_F4_PER_THREAD)        // 1024
#define FILL_BLOCKS (16777216 / FILL_F4_PER_BLOCK)          // 16384
#define GRID_BLOCKS (LOGITS_BLOCKS + FILL_BLOCKS)           // 16896

__global__ __launch_bounds__(256, 3)   // 85-reg budget: no spills
void router_fused_kernel(const float* __restrict__ hs,
                         const float* __restrict__ wr,
                         float* __restrict__ out) {
    __shared__ float part[2][4][TPW][N_EXP];    // 512 B, logits blocks only
    const unsigned bid = blockIdx.x;

    if (bid >= LOGITS_BLOCKS) {
        // ------------------------- fill branch -------------------------
        float4* __restrict__ out4 = (float4*)(out + IDX_OFF);
        const size_t base = (size_t)(bid - LOGITS_BLOCKS) * FILL_F4_PER_BLOCK
                          + threadIdx.x;
#pragma unroll
        for (int j = 0; j < FILL_F4_PER_THREAD; j++) {
            const size_t i = base + (size_t)j * 256;
            const float v = (float)((i >> 9) & (T_TOKENS - 1));
            __stcs(&out4[i], make_float4(v, v, v, v));
        }
        return;
    }

    // ------------------------- logits branch -------------------------
    const int warp  = threadIdx.x >> 5;
    const int lane  = threadIdx.x & 31;
    const int half  = warp >> 2;                 // 0 or 1: hidden half
    const int wpair = warp & 3;                  // 0..3: token group
    const int t0 = ((int)bid * 4 + wpair) * TPW; // 2 tokens per warp

    const float4* __restrict__ hs4 = (const float4*)hs;
    const float4* __restrict__ w4  = (const float4*)wr;

    float acc[TPW][N_EXP];
#pragma unroll
    for (int a = 0; a < TPW; a++)
#pragma unroll
        for (int e = 0; e < N_EXP; e++) acc[a][e] = 0.f;

    const int ibase = half * H4_HALF;
#pragma unroll 2
    for (int ii = 0; ii < H4_HALF / 32; ii++) {  // 8 iterations (half of R8)
        const int i = ibase + ii * 32 + lane;
        float4 x[TPW];
#pragma unroll
        for (int a = 0; a < TPW; a++)
            x[a] = hs4[(size_t)(t0 + a) * H4 + i];
#pragma unroll
        for (int e = 0; e < N_EXP; e++) {
            const float4 wv = __ldg(&w4[e * H4 + i]);
#pragma unroll
            for (int a = 0; a < TPW; a++) {
                acc[a][e] += x[a].x * wv.x + x[a].y * wv.y
                           + x[a].z * wv.z + x[a].w * wv.w;
            }
        }
    }

    // butterfly warp reduction
#pragma unroll
    for (int a = 0; a < TPW; a++)
#pragma unroll
        for (int e = 0; e < N_EXP; e++)
#pragma unroll
            for (int o = 16; o > 0; o >>= 1)
                acc[a][e] += __shfl_xor_sync(0xffffffffu, acc[a][e], o);

    if (lane == 0) {
#pragma unroll
        for (int a = 0; a < TPW; a++)
#pragma unroll
            for (int e = 0; e < N_EXP; e++)
                part[half][wpair][a][e] = acc[a][e];
    }
    __syncthreads();

    if (half == 0 && lane == 0) {
#pragma unroll
        for (int a = 0; a < TPW; a++) {
            const int t = t0 + a;
            float lg[N_EXP];
#pragma unroll
            for (int e = 0; e < N_EXP; e++)
                lg[e] = part[0][wpair][a][e] + part[1][wpair][a][e];

            float b1 = -CUDART_INF_F; int i1 = 0;
#pragma unroll
            for (int e = 0; e < N_EXP; e++)
                if (lg[e] > b1) { b1 = lg[e]; i1 = e; }
            float b2 = -CUDART_INF_F; int i2 = -1;
#pragma unroll
            for (int e = 0; e < N_EXP; e++)
                if (e != i1 && lg[e] > b2) { b2 = lg[e]; i2 = e; }

            const float s1 = 1.f / (1.f + __expf(-b1));
            const float s2 = 1.f / (1.f + __expf(-b2));
#pragma unroll
            for (int e = 0; e < N_EXP; e++) {
                const float s = (e == i1) ? s1 : ((e == i2) ? s2 : 0.f);
                out[SCORES_OFF + (size_t)e * T_TOKENS + t] = s;
                out[PROBS_OFF  + (size_t)e * T_TOKENS + t] = s;
            }
        }
    }
}

extern "C" void kernel_launch(void* const* d_in, const int* in_sizes, int n_in,
                              void* d_out, int out_size) {
    const float* hs = (const float*)d_in[0];  // [T, H] fp32
    const float* wr = (const float*)d_in[1];  // [E, H] fp32
    float* out = (float*)d_out;

    router_fused_kernel<<<GRID_BLOCKS, 256>>>(hs, wr, out);
}

// round 13
// speedup vs baseline: 1.0883x; 1.0883x over previous
#include <cuda_runtime.h>
#include <cuda_bf16.h>
#include <math_constants.h>

// Problem constants
#define T_TOKENS 4096
#define HIDDEN   2048
#define N_EXP    8
#define H4       (HIDDEN / 4)          // 512 float4 per hidden row

// Output layout (floats), outputs concatenated:
//   [0, 32768)                router_scores [E, T]
//   [32768, +67108864)        router_indices [E*T, H] (value = t, as float)
//   [67141632, 67174400)      router_probs [E*T, 1] == scores flattened
#define SCORES_OFF 0
#define IDX_OFF    (N_EXP * T_TOKENS)                       // 32768
#define IDX_ELEMS  ((size_t)N_EXP * T_TOKENS * HIDDEN)      // 67108864
#define PROBS_OFF  (IDX_OFF + IDX_ELEMS)                    // 67141632

// Fused grid, blockDim = 128 (best measured configuration, R8: 43.5us):
//   ids [0, 512)        logits blocks: 4 warps x 2 tokens = 8 tokens/block
//   ids [512, 16896)    fill blocks: 128 thr x 8 float4 = 1024 f4/block
// Logits confined to the first wave (reads overlap early fill writes);
// short fill CTAs avoid straggler waves; 80 regs -> no spills, occ 6 CTA/SM.
#define LOGITS_BLOCKS 512
#define TPW 2
#define FILL_F4_PER_THREAD 8
#define FILL_F4_PER_BLOCK (128 * FILL_F4_PER_THREAD)        // 1024
#define FILL_BLOCKS (16777216 / FILL_F4_PER_BLOCK)          // 16384
#define GRID_BLOCKS (LOGITS_BLOCKS + FILL_BLOCKS)           // 16896

__global__ __launch_bounds__(128, 6)
void router_fused_kernel(const float* __restrict__ hs,
                         const float* __restrict__ wr,
                         float* __restrict__ out) {
    const unsigned bid = blockIdx.x;

    if (bid >= LOGITS_BLOCKS) {
        // ------------------------- fill branch -------------------------
        float4* __restrict__ out4 = (float4*)(out + IDX_OFF);
        const size_t base = (size_t)(bid - LOGITS_BLOCKS) * FILL_F4_PER_BLOCK
                          + threadIdx.x;
#pragma unroll
        for (int j = 0; j < FILL_F4_PER_THREAD; j++) {
            const size_t i = base + (size_t)j * 128;
            const float v = (float)((i >> 9) & (T_TOKENS - 1));
            __stcs(&out4[i], make_float4(v, v, v, v));
        }
        return;
    }

    // ------------------------- logits branch -------------------------
    const int warp = threadIdx.x >> 5;
    const int lane = threadIdx.x & 31;
    const int t0 = ((int)bid * 4 + warp) * TPW;      // 2 tokens per warp

    const float4* __restrict__ hs4 = (const float4*)hs;
    const float4* __restrict__ w4  = (const float4*)wr;

    float acc[TPW][N_EXP];
#pragma unroll
    for (int a = 0; a < TPW; a++)
#pragma unroll
        for (int e = 0; e < N_EXP; e++) acc[a][e] = 0.f;

#pragma unroll 2
    for (int ii = 0; ii < H4 / 32; ii++) {           // 16 iterations
        const int i = ii * 32 + lane;
        float4 x[TPW];
#pragma unroll
        for (int a = 0; a < TPW; a++)
            x[a] = hs4[(size_t)(t0 + a) * H4 + i];
#pragma unroll
        for (int e = 0; e < N_EXP; e++) {
            const float4 wv = __ldg(&w4[e * H4 + i]);
#pragma unroll
            for (int a = 0; a < TPW; a++) {
                acc[a][e] += x[a].x * wv.x + x[a].y * wv.y
                           + x[a].z * wv.z + x[a].w * wv.w;
            }
        }
    }

    // butterfly warp reduction
#pragma unroll
    for (int a = 0; a < TPW; a++)
#pragma unroll
        for (int e = 0; e < N_EXP; e++)
#pragma unroll
            for (int o = 16; o > 0; o >>= 1)
                acc[a][e] += __shfl_xor_sync(0xffffffffu, acc[a][e], o);

    if (lane == 0) {
#pragma unroll
        for (int a = 0; a < TPW; a++) {
            const int t = t0 + a;
            float b1 = -CUDART_INF_F; int i1 = 0;
#pragma unroll
            for (int e = 0; e < N_EXP; e++)
                if (acc[a][e] > b1) { b1 = acc[a][e]; i1 = e; }
            float b2 = -CUDART_INF_F; int i2 = -1;
#pragma unroll
            for (int e = 0; e < N_EXP; e++)
                if (e != i1 && acc[a][e] > b2) { b2 = acc[a][e]; i2 = e; }

            const float s1 = 1.f / (1.f + __expf(-b1));
            const float s2 = 1.f / (1.f + __expf(-b2));
#pragma unroll
            for (int e = 0; e < N_EXP; e++) {
                const float s = (e == i1) ? s1 : ((e == i2) ? s2 : 0.f);
                out[SCORES_OFF + (size_t)e * T_TOKENS + t] = s;
                out[PROBS_OFF  + (size_t)e * T_TOKENS + t] = s;
            }
        }
    }
}

extern "C" void kernel_launch(void* const* d_in, const int* in_sizes, int n_in,
                              void* d_out, int out_size) {
    const float* hs = (const float*)d_in[0];  // [T, H] fp32
    const float* wr = (const float*)d_in[1];  // [E, H] fp32
    float* out = (float*)d_out;

    router_fused_kernel<<<GRID_BLOCKS, 128>>>(hs, wr, out);
}